// round 2
// baseline (speedup 1.0000x reference)
#include <cuda_runtime.h>
#include <cuda_bf16.h>

// ---------------------------------------------------------------------------
// mLSTM block, GB300 sm_103a. Round 1: tf32 mma.sync, fused 6-way projection.
//   N = 16384 rows (8*2048), D = 1024, P = 2048, H = 1024.
// Pipeline:
//   round/repack weights to tf32 -> LN1 -> GEMM(up) -> GEMM(adj)
//   -> GEMM(proj, N=6144 = q|k|v|i|f|o concatenated, k pre-scaled by 1/8)
//   -> elementwise mLSTM + LN2 * sigmoid(adj) -> GEMM(down) + bias + x
// All scratch in __device__ globals. Graph-capturable: kernel launches only.
// ---------------------------------------------------------------------------

#define NROWS 16384
#define SZF   (16384ull * 1024ull)       // one [N,1024] fp32 plane (elements)
#define M1F   (1024ull * 1024ull)        // one [1024,1024] weight (elements)

// xn/y(1, aliased) + up(2) + adj(1) + proj(6) = 10 planes
__device__ float g_buf[10ull * SZF];
// rounded weights: up(2M) adj(2M) cat(6M) down(1M) + bias_cat(8K)
__device__ float g_wr[11ull * M1F + 8192ull];

__device__ __forceinline__ float tf32r(float x) {
    unsigned int u;
    asm("cvt.rna.tf32.f32 %0, %1;" : "=r"(u) : "f"(x));
    return __uint_as_float(u);
}

__device__ __forceinline__ void cpasync16(unsigned int dst, const void* src) {
    asm volatile("cp.async.cg.shared.global [%0], [%1], 16;" :: "r"(dst), "l"(src));
}

// ---------------------------------------------------------------------------
// Weight rounding: fp32 -> tf32 bits (round-to-nearest), vectorized by 4.
// ---------------------------------------------------------------------------
__global__ void round_k(const float* __restrict__ in, float* __restrict__ out, int n4) {
    int i = blockIdx.x * blockDim.x + threadIdx.x;
    if (i < n4) {
        float4 v = reinterpret_cast<const float4*>(in)[i];
        v.x = tf32r(v.x); v.y = tf32r(v.y); v.z = tf32r(v.z); v.w = tf32r(v.w);
        reinterpret_cast<float4*>(out)[i] = v;
    }
}

// Repack one [1024,1024] weight into a column-slice of the [1024,6144]
// concatenated projection weight, tf32-rounded and scaled.
// out6 points at column offset j*1024 of the cat matrix (row stride 6144).
__global__ void repack_k(const float* __restrict__ in, float* __restrict__ out6,
                         float scale) {
    int i = blockIdx.x * blockDim.x + threadIdx.x;   // over 1024*256 float4s
    if (i < 1024 * 256) {
        int k = i >> 8, c = i & 255;                 // row k, float4-col c
        float4 v = reinterpret_cast<const float4*>(in)[i];
        v.x = tf32r(v.x * scale); v.y = tf32r(v.y * scale);
        v.z = tf32r(v.z * scale); v.w = tf32r(v.w * scale);
        reinterpret_cast<float4*>(out6)[(size_t)k * 1536 + c] = v;
    }
}

__global__ void biascat_k(const float* __restrict__ in, float* __restrict__ out,
                          float scale) {
    int i = blockIdx.x * blockDim.x + threadIdx.x;
    if (i < 1024) out[i] = in[i] * scale;
}

// ---------------------------------------------------------------------------
// Block reduction over 256 threads (sum + sumsq), result broadcast to all.
// ---------------------------------------------------------------------------
__device__ __forceinline__ void block_reduce2(float& s, float& ss, float* red) {
#pragma unroll
    for (int o = 16; o > 0; o >>= 1) {
        s  += __shfl_xor_sync(0xffffffffu, s,  o);
        ss += __shfl_xor_sync(0xffffffffu, ss, o);
    }
    int w = threadIdx.x >> 5;
    if ((threadIdx.x & 31) == 0) { red[w] = s; red[8 + w] = ss; }
    __syncthreads();
    s = 0.f; ss = 0.f;
#pragma unroll
    for (int i = 0; i < 8; i++) { s += red[i]; ss += red[8 + i]; }
}

// ---------------------------------------------------------------------------
// LN1: one block per row of 1024, 256 threads * 4 elems. Output tf32-rounded.
// ---------------------------------------------------------------------------
__global__ void ln_kernel(const float* __restrict__ x, const float* __restrict__ g,
                          const float* __restrict__ b, float* __restrict__ o) {
    __shared__ float red[16];
    int tid = threadIdx.x;
    size_t base = (size_t)blockIdx.x * 1024 + (size_t)tid * 4;
    float4 v = *reinterpret_cast<const float4*>(x + base);
    float s  = v.x + v.y + v.z + v.w;
    float ss = v.x*v.x + v.y*v.y + v.z*v.z + v.w*v.w;
    block_reduce2(s, ss, red);
    float mean = s * (1.f / 1024.f);
    float var  = ss * (1.f / 1024.f) - mean * mean;
    float rs = rsqrtf(var + 1e-3f);
    float4 gg = *reinterpret_cast<const float4*>(g + tid * 4);
    float4 bb = *reinterpret_cast<const float4*>(b + tid * 4);
    float4 r;
    r.x = tf32r((v.x - mean) * rs * gg.x + bb.x);
    r.y = tf32r((v.y - mean) * rs * gg.y + bb.y);
    r.z = tf32r((v.z - mean) * rs * gg.z + bb.z);
    r.w = tf32r((v.w - mean) * rs * gg.w + bb.w);
    *reinterpret_cast<float4*>(o + base) = r;
}

// ---------------------------------------------------------------------------
// Elementwise mLSTM gates + LN2 * sigmoid(x_adj). One block per row.
// proj rows are 6144 wide: [q | k(pre-scaled) | v | i | f | o].
// Output tf32-rounded.
// ---------------------------------------------------------------------------
__global__ void ew_kernel(const float* __restrict__ proj,
                          const float* __restrict__ adj, const float* __restrict__ g2,
                          const float* __restrict__ b2, float* __restrict__ y) {
    __shared__ float red[16];
    int tid = threadIdx.x;
    size_t base6 = (size_t)blockIdx.x * 6144 + (size_t)tid * 4;
    size_t base  = (size_t)blockIdx.x * 1024 + (size_t)tid * 4;
    float4 q4 = *reinterpret_cast<const float4*>(proj + base6);
    float4 k4 = *reinterpret_cast<const float4*>(proj + base6 + 1024);
    float4 v4 = *reinterpret_cast<const float4*>(proj + base6 + 2048);
    float4 i4 = *reinterpret_cast<const float4*>(proj + base6 + 3072);
    float4 f4 = *reinterpret_cast<const float4*>(proj + base6 + 4096);
    float4 o4 = *reinterpret_cast<const float4*>(proj + base6 + 5120);
    float qq[4] = {q4.x, q4.y, q4.z, q4.w};
    float kk[4] = {k4.x, k4.y, k4.z, k4.w};
    float vv[4] = {v4.x, v4.y, v4.z, v4.w};
    float ii[4] = {i4.x, i4.y, i4.z, i4.w};
    float ff[4] = {f4.x, f4.y, f4.z, f4.w};
    float oo[4] = {o4.x, o4.y, o4.z, o4.w};
    float h[4], s = 0.f, ss = 0.f;
#pragma unroll
    for (int e = 0; e < 4; e++) {
        float sig_o = 1.f / (1.f + expf(-oo[e]));
        float m  = fmaxf(ff[e], ii[e]);
        float fg = expf(ff[e] - m);
        float c  = fg * vv[e] * kk[e];
        float den = fmaxf(fabsf(kk[e] * qq[e]), 1.f);
        float hh = sig_o * (c * qq[e]) / den;
        h[e] = hh; s += hh; ss += hh * hh;
    }
    block_reduce2(s, ss, red);
    float mean = s * (1.f / 1024.f);
    float var  = ss * (1.f / 1024.f) - mean * mean;
    float rs = rsqrtf(var + 1e-3f);
    float4 g4 = *reinterpret_cast<const float4*>(g2 + tid * 4);
    float4 bb4 = *reinterpret_cast<const float4*>(b2 + tid * 4);
    float4 a4 = *reinterpret_cast<const float4*>(adj + base);
    float ga[4] = {g4.x, g4.y, g4.z, g4.w};
    float ba[4] = {bb4.x, bb4.y, bb4.z, bb4.w};
    float aa[4] = {a4.x, a4.y, a4.z, a4.w};
    float out[4];
#pragma unroll
    for (int e = 0; e < 4; e++) {
        float sig_a = 1.f / (1.f + expf(-aa[e]));
        out[e] = tf32r(((h[e] - mean) * rs * ga[e] + ba[e]) * sig_a);
    }
    float4 r = {out[0], out[1], out[2], out[3]};
    *reinterpret_cast<float4*>(y + base) = r;
}

// ---------------------------------------------------------------------------
// GEMM: C[M,N] = (A[M,K] @ B[K,N] + bias) (+ resid) (tf32-round opt)
// CTA tile 128x128x32, 256 threads, warp tile 32x64, mma.m16n8k8.tf32.
// cp.async double-buffered. SMEM pads chosen for conflict-free fragment LDS:
//   As stride 36 floats, Bs stride 136.
// Requires M%128==0, N%128==0, K%32==0 (always true here).
// ---------------------------------------------------------------------------
#define AS_STAGE_F 4608u   // 128*36 floats
#define BS_STAGE_F 4352u   // 32*136 floats
#define SMEM_BYTES 71680u  // (2*4608 + 2*4352)*4

template<bool RESID, bool ROUND>
__global__ void gemm_tf32(const float* __restrict__ A, const float* __restrict__ Bw,
                          const float* __restrict__ bias, const float* __restrict__ resid,
                          float* __restrict__ C, int N, int K) {
    extern __shared__ float sm[];
    const int tid = threadIdx.x;
    const int lane = tid & 31, wid = tid >> 5;
    const int wm = wid & 3, wn = wid >> 2;          // 4 warps in M, 2 in N
    const int bm = blockIdx.y * 128, bn = blockIdx.x * 128;
    const int qrow = lane >> 2, qcol = lane & 3;

    float acc[2][8][4];
#pragma unroll
    for (int mi = 0; mi < 2; mi++)
#pragma unroll
        for (int ni = 0; ni < 8; ni++)
#pragma unroll
            for (int e = 0; e < 4; e++) acc[mi][ni][e] = 0.f;

    unsigned int sbase = (unsigned int)__cvta_generic_to_shared(sm);
    const float* ag = A + (size_t)bm * K;
    const float* bg = Bw + bn;

#define LOAD_TILES(stg, k0_) do {                                              \
        int k0 = (k0_);                                                        \
        unsigned int sa = sbase + (stg) * (AS_STAGE_F * 4u);                   \
        unsigned int sb = sbase + 2u * AS_STAGE_F * 4u + (stg) * (BS_STAGE_F * 4u); \
        _Pragma("unroll")                                                      \
        for (int i = 0; i < 4; i++) {                                          \
            int c = tid + i * 256;                                             \
            int r = c >> 3, c4 = (c & 7) << 2;                                 \
            cpasync16(sa + (unsigned int)r * 144u + (unsigned int)c4 * 4u,     \
                      ag + (size_t)r * K + k0 + c4);                           \
        }                                                                      \
        _Pragma("unroll")                                                      \
        for (int i = 0; i < 4; i++) {                                          \
            int c = tid + i * 256;                                             \
            int r = c >> 5, c4 = (c & 31) << 2;                                \
            cpasync16(sb + (unsigned int)r * 544u + (unsigned int)c4 * 4u,     \
                      bg + (size_t)(k0 + r) * N + c4);                         \
        }                                                                      \
    } while (0)

    LOAD_TILES(0, 0);
    asm volatile("cp.async.commit_group;" ::: "memory");

    const int nk = K >> 5;
    for (int kt = 0; kt < nk; kt++) {
        int buf = kt & 1;
        if (kt + 1 < nk) LOAD_TILES(buf ^ 1, (kt + 1) << 5);
        asm volatile("cp.async.commit_group;" ::: "memory");
        asm volatile("cp.async.wait_group 1;" ::: "memory");
        __syncthreads();

        const float* as = sm + buf * AS_STAGE_F + wm * (32 * 36);
        const float* bs = sm + 2 * AS_STAGE_F + buf * BS_STAGE_F + wn * 64;
#pragma unroll
        for (int kk = 0; kk < 4; kk++) {
            unsigned int a[2][4], b[8][2];
#pragma unroll
            for (int mi = 0; mi < 2; mi++) {
                const unsigned int* ap = reinterpret_cast<const unsigned int*>(
                    as + (mi * 16 + qrow) * 36 + kk * 8 + qcol);
                a[mi][0] = ap[0];
                a[mi][1] = ap[8 * 36];
                a[mi][2] = ap[4];
                a[mi][3] = ap[8 * 36 + 4];
            }
#pragma unroll
            for (int ni = 0; ni < 8; ni++) {
                const unsigned int* bp = reinterpret_cast<const unsigned int*>(
                    bs + (kk * 8 + qcol) * 136 + ni * 8 + qrow);
                b[ni][0] = bp[0];
                b[ni][1] = bp[4 * 136];
            }
#pragma unroll
            for (int mi = 0; mi < 2; mi++)
#pragma unroll
                for (int ni = 0; ni < 8; ni++)
                    asm volatile(
                        "mma.sync.aligned.m16n8k8.row.col.f32.tf32.tf32.f32 "
                        "{%0,%1,%2,%3}, {%4,%5,%6,%7}, {%8,%9}, {%0,%1,%2,%3};"
                        : "+f"(acc[mi][ni][0]), "+f"(acc[mi][ni][1]),
                          "+f"(acc[mi][ni][2]), "+f"(acc[mi][ni][3])
                        : "r"(a[mi][0]), "r"(a[mi][1]), "r"(a[mi][2]), "r"(a[mi][3]),
                          "r"(b[ni][0]), "r"(b[ni][1]));
        }
        __syncthreads();
    }
#undef LOAD_TILES

    // Epilogue: (acc + bias) [+ resid] [tf32 round], float2 stores.
#pragma unroll
    for (int mi = 0; mi < 2; mi++) {
#pragma unroll
        for (int ni = 0; ni < 8; ni++) {
            int r0  = bm + wm * 32 + mi * 16 + qrow;
            int col = bn + wn * 64 + ni * 8 + qcol * 2;
            float2 bb = *reinterpret_cast<const float2*>(bias + col);
            float2 v0, v1;
            v0.x = acc[mi][ni][0] + bb.x;
            v0.y = acc[mi][ni][1] + bb.y;
            v1.x = acc[mi][ni][2] + bb.x;
            v1.y = acc[mi][ni][3] + bb.y;
            if (RESID) {
                float2 ra = *reinterpret_cast<const float2*>(resid + (size_t)r0 * N + col);
                float2 rb = *reinterpret_cast<const float2*>(resid + (size_t)(r0 + 8) * N + col);
                v0.x += ra.x; v0.y += ra.y;
                v1.x += rb.x; v1.y += rb.y;
            }
            if (ROUND) {
                v0.x = tf32r(v0.x); v0.y = tf32r(v0.y);
                v1.x = tf32r(v1.x); v1.y = tf32r(v1.y);
            }
            *reinterpret_cast<float2*>(C + (size_t)r0 * N + col) = v0;
            *reinterpret_cast<float2*>(C + (size_t)(r0 + 8) * N + col) = v1;
        }
    }
}

// ---------------------------------------------------------------------------
// Launch
// ---------------------------------------------------------------------------
extern "C" void kernel_launch(void* const* d_in, const int* in_sizes, int n_in,
                              void* d_out, int out_size) {
    const float* x      = (const float*)d_in[0];
    const float* ln1g   = (const float*)d_in[1];
    const float* ln1b   = (const float*)d_in[2];
    const float* W_up   = (const float*)d_in[3];
    const float* b_up   = (const float*)d_in[4];
    const float* W_adj  = (const float*)d_in[5];
    const float* b_adj  = (const float*)d_in[6];
    const float* W_q = (const float*)d_in[7];   const float* b_q = (const float*)d_in[8];
    const float* W_k = (const float*)d_in[9];   const float* b_k = (const float*)d_in[10];
    const float* W_v = (const float*)d_in[11];  const float* b_v = (const float*)d_in[12];
    const float* W_i = (const float*)d_in[13];  const float* b_i = (const float*)d_in[14];
    const float* W_f = (const float*)d_in[15];  const float* b_f = (const float*)d_in[16];
    const float* W_o = (const float*)d_in[17];  const float* b_o = (const float*)d_in[18];
    const float* ln2g   = (const float*)d_in[19];
    const float* ln2b   = (const float*)d_in[20];
    const float* W_down = (const float*)d_in[21];
    const float* b_down = (const float*)d_in[22];
    float* out = (float*)d_out;

    void* p;
    cudaGetSymbolAddress(&p, g_buf); float* buf = (float*)p;
    cudaGetSymbolAddress(&p, g_wr);  float* wr  = (float*)p;

    float* xn   = buf;                 // also reused as y (xn dead after up)
    float* up   = buf + 1 * SZF;
    float* adj  = buf + 3 * SZF;
    float* proj = buf + 4 * SZF;       // 6 planes, rows of 6144
    float* y    = xn;

    float* wr_up   = wr;
    float* wr_adj  = wr + 2 * M1F;
    float* wr_cat  = wr + 4 * M1F;     // [1024, 6144]
    float* wr_down = wr + 10 * M1F;
    float* b_cat   = wr + 11 * M1F;    // 6144 floats

    cudaFuncSetAttribute((const void*)gemm_tf32<false, true>,
                         cudaFuncAttributeMaxDynamicSharedMemorySize, SMEM_BYTES);
    cudaFuncSetAttribute((const void*)gemm_tf32<false, false>,
                         cudaFuncAttributeMaxDynamicSharedMemorySize, SMEM_BYTES);
    cudaFuncSetAttribute((const void*)gemm_tf32<true, false>,
                         cudaFuncAttributeMaxDynamicSharedMemorySize, SMEM_BYTES);

    // Round / repack weights to tf32 (round-to-nearest -> unbiased inputs).
    round_k<<<2048, 256>>>(W_up,  wr_up,  (int)(2 * M1F / 4));
    round_k<<<2048, 256>>>(W_adj, wr_adj, (int)(2 * M1F / 4));
    round_k<<<1024, 256>>>(W_down, wr_down, (int)(M1F / 4));
    const float* Wp[6] = {W_q, W_k, W_v, W_i, W_f, W_o};
    const float* bp[6] = {b_q, b_k, b_v, b_i, b_f, b_o};
    for (int j = 0; j < 6; j++) {
        float scale = (j == 1) ? 0.125f : 1.f;   // fold 1/sqrt(64) into k
        repack_k<<<1024, 256>>>(Wp[j], wr_cat + (size_t)j * 1024, scale);
        biascat_k<<<4, 256>>>(bp[j], b_cat + (size_t)j * 1024, scale);
    }

    // LN1
    ln_kernel<<<NROWS, 256>>>(x, ln1g, ln1b, xn);

    // up: [N,1024] @ [1024,2048]
    gemm_tf32<false, true><<<dim3(16, 128), 256, SMEM_BYTES>>>(
        xn, wr_up, b_up, nullptr, up, 2048, 1024);

    // adj: [N,2048] @ [2048,1024]
    gemm_tf32<false, true><<<dim3(8, 128), 256, SMEM_BYTES>>>(
        up, wr_adj, b_adj, nullptr, adj, 1024, 2048);

    // fused projections: [N,1024] @ [1024,6144]
    gemm_tf32<false, false><<<dim3(48, 128), 256, SMEM_BYTES>>>(
        adj, wr_cat, b_cat, nullptr, proj, 6144, 1024);

    // gates + LN2 * sigmoid(adj)
    ew_kernel<<<NROWS, 256>>>(proj, adj, ln2g, ln2b, y);

    // down: [N,1024] @ [1024,1024] + b_down + x
    gemm_tf32<true, false><<<dim3(8, 128), 256, SMEM_BYTES>>>(
        y, wr_down, b_down, x, out, 1024, 1024);
}

// round 4
// speedup vs baseline: 2.3291x; 2.3291x over previous
#include <cuda_runtime.h>
#include <cuda_bf16.h>

// ---------------------------------------------------------------------------
// mLSTM block, GB300 sm_103a. Round 3: bf16 mma.m16n8k16 + ldmatrix.
//   N = 16384 rows, D = 1024, P = 2048, H = 1024.
// Pipeline:
//   cvt/repack weights to bf16 -> LN1(bf16 out) -> GEMM(up) -> GEMM(adj)
//   -> GEMM(proj, N=6144 concat q|k|v|i|f|o, k pre-scaled 1/8)
//   -> elementwise mLSTM + LN2*sigmoid(adj) (bf16) -> GEMM(down)+bias+x (fp32)
// All scratch in __device__ globals. Graph-capturable.
// ---------------------------------------------------------------------------

#define NROWS 16384
#define SZB (16384ull * 1024ull)     // one [N,1024] plane (elements)
#define M1  (1024ull * 1024ull)

// planes: xn/y(1 shared) + up(2) + adj(1) + proj(6) = 10
__device__ __align__(16) __nv_bfloat16 g_act[10ull * SZB];
// weights bf16: up(2M) adj(2M) cat(6M) down(1M)
__device__ __align__(16) __nv_bfloat16 g_w[11ull * M1];
__device__ __align__(16) float g_bcat[6144];

__device__ __forceinline__ unsigned pack_bf2(float a, float b) {
    __nv_bfloat162 h = __floats2bfloat162_rn(a, b);
    return *reinterpret_cast<unsigned*>(&h);
}
__device__ __forceinline__ float4 ld_bf4(const __nv_bfloat16* p) {
    uint2 u = *reinterpret_cast<const uint2*>(p);
    __nv_bfloat162 a = *reinterpret_cast<__nv_bfloat162*>(&u.x);
    __nv_bfloat162 b = *reinterpret_cast<__nv_bfloat162*>(&u.y);
    float4 r;
    r.x = __bfloat162float(a.x); r.y = __bfloat162float(a.y);
    r.z = __bfloat162float(b.x); r.w = __bfloat162float(b.y);
    return r;
}
__device__ __forceinline__ void cpasync16(unsigned dst, const void* src) {
    asm volatile("cp.async.cg.shared.global [%0], [%1], 16;" :: "r"(dst), "l"(src));
}
__device__ __forceinline__ void ldsm_x4(unsigned& r0, unsigned& r1, unsigned& r2,
                                        unsigned& r3, unsigned a) {
    asm volatile("ldmatrix.sync.aligned.m8n8.x4.shared.b16 {%0,%1,%2,%3}, [%4];"
                 : "=r"(r0), "=r"(r1), "=r"(r2), "=r"(r3) : "r"(a));
}
__device__ __forceinline__ void ldsm_x4t(unsigned& r0, unsigned& r1, unsigned& r2,
                                         unsigned& r3, unsigned a) {
    asm volatile("ldmatrix.sync.aligned.m8n8.x4.trans.shared.b16 {%0,%1,%2,%3}, [%4];"
                 : "=r"(r0), "=r"(r1), "=r"(r2), "=r"(r3) : "r"(a));
}
__device__ __forceinline__ void mma_bf16(float* c, const unsigned* a, const unsigned* b) {
    asm volatile("mma.sync.aligned.m16n8k16.row.col.f32.bf16.bf16.f32 "
                 "{%0,%1,%2,%3}, {%4,%5,%6,%7}, {%8,%9}, {%0,%1,%2,%3};"
                 : "+f"(c[0]), "+f"(c[1]), "+f"(c[2]), "+f"(c[3])
                 : "r"(a[0]), "r"(a[1]), "r"(a[2]), "r"(a[3]), "r"(b[0]), "r"(b[1]));
}

// ---------------------------------------------------------------------------
// Weight conversion fp32 -> bf16 (rne), vectorized by 4.
// ---------------------------------------------------------------------------
__global__ void cvt_k(const float* __restrict__ in, __nv_bfloat16* __restrict__ out, int n4) {
    int i = blockIdx.x * blockDim.x + threadIdx.x;
    if (i < n4) {
        float4 v = reinterpret_cast<const float4*>(in)[i];
        uint2 u;
        u.x = pack_bf2(v.x, v.y); u.y = pack_bf2(v.z, v.w);
        reinterpret_cast<uint2*>(out)[i] = u;
    }
}

// Repack one [1024,1024] weight into column-slice of [1024,6144] cat (bf16, scaled).
__global__ void repack_k(const float* __restrict__ in, __nv_bfloat16* __restrict__ out6,
                         float scale) {
    int i = blockIdx.x * blockDim.x + threadIdx.x;   // 1024*256 float4s
    if (i < 1024 * 256) {
        int k = i >> 8, c = i & 255;
        float4 v = reinterpret_cast<const float4*>(in)[i];
        uint2 u;
        u.x = pack_bf2(v.x * scale, v.y * scale);
        u.y = pack_bf2(v.z * scale, v.w * scale);
        *reinterpret_cast<uint2*>(out6 + (size_t)k * 6144 + c * 4) = u;
    }
}

__global__ void biascat_k(const float* __restrict__ in, float* __restrict__ out, float scale) {
    int i = blockIdx.x * blockDim.x + threadIdx.x;
    if (i < 1024) out[i] = in[i] * scale;
}

// ---------------------------------------------------------------------------
// Block reduce (sum + sumsq) over 256 threads.
// ---------------------------------------------------------------------------
__device__ __forceinline__ void block_reduce2(float& s, float& ss, float* red) {
#pragma unroll
    for (int o = 16; o > 0; o >>= 1) {
        s  += __shfl_xor_sync(0xffffffffu, s,  o);
        ss += __shfl_xor_sync(0xffffffffu, ss, o);
    }
    int w = threadIdx.x >> 5;
    if ((threadIdx.x & 31) == 0) { red[w] = s; red[8 + w] = ss; }
    __syncthreads();
    s = 0.f; ss = 0.f;
#pragma unroll
    for (int i = 0; i < 8; i++) { s += red[i]; ss += red[8 + i]; }
}

// ---------------------------------------------------------------------------
// LN1: fp32 in, bf16 out. One block / row.
// ---------------------------------------------------------------------------
__global__ void ln_kernel(const float* __restrict__ x, const float* __restrict__ g,
                          const float* __restrict__ b, __nv_bfloat16* __restrict__ o) {
    __shared__ float red[16];
    int tid = threadIdx.x;
    size_t base = (size_t)blockIdx.x * 1024 + (size_t)tid * 4;
    float4 v = *reinterpret_cast<const float4*>(x + base);
    float s  = v.x + v.y + v.z + v.w;
    float ss = v.x*v.x + v.y*v.y + v.z*v.z + v.w*v.w;
    block_reduce2(s, ss, red);
    float mean = s * (1.f / 1024.f);
    float var  = ss * (1.f / 1024.f) - mean * mean;
    float rs = rsqrtf(var + 1e-3f);
    float4 gg = *reinterpret_cast<const float4*>(g + tid * 4);
    float4 bb = *reinterpret_cast<const float4*>(b + tid * 4);
    uint2 u;
    u.x = pack_bf2((v.x - mean) * rs * gg.x + bb.x, (v.y - mean) * rs * gg.y + bb.y);
    u.y = pack_bf2((v.z - mean) * rs * gg.z + bb.z, (v.w - mean) * rs * gg.w + bb.w);
    *reinterpret_cast<uint2*>(o + base) = u;
}

// ---------------------------------------------------------------------------
// Elementwise mLSTM + LN2 * sigmoid(adj). bf16 in/out. One block / row.
// proj rows 6144 wide: [q | k(scaled) | v | i | f | o].
// ---------------------------------------------------------------------------
__global__ void ew_kernel(const __nv_bfloat16* __restrict__ proj,
                          const __nv_bfloat16* __restrict__ adj,
                          const float* __restrict__ g2, const float* __restrict__ b2,
                          __nv_bfloat16* __restrict__ y) {
    __shared__ float red[16];
    int tid = threadIdx.x;
    size_t base6 = (size_t)blockIdx.x * 6144 + (size_t)tid * 4;
    size_t base  = (size_t)blockIdx.x * 1024 + (size_t)tid * 4;
    float4 q4 = ld_bf4(proj + base6);
    float4 k4 = ld_bf4(proj + base6 + 1024);
    float4 v4 = ld_bf4(proj + base6 + 2048);
    float4 i4 = ld_bf4(proj + base6 + 3072);
    float4 f4 = ld_bf4(proj + base6 + 4096);
    float4 o4 = ld_bf4(proj + base6 + 5120);
    float qq[4] = {q4.x, q4.y, q4.z, q4.w};
    float kk[4] = {k4.x, k4.y, k4.z, k4.w};
    float vv[4] = {v4.x, v4.y, v4.z, v4.w};
    float ii[4] = {i4.x, i4.y, i4.z, i4.w};
    float ff[4] = {f4.x, f4.y, f4.z, f4.w};
    float oo[4] = {o4.x, o4.y, o4.z, o4.w};
    float h[4], s = 0.f, ss = 0.f;
#pragma unroll
    for (int e = 0; e < 4; e++) {
        float sig_o = 1.f / (1.f + expf(-oo[e]));
        float m  = fmaxf(ff[e], ii[e]);
        float fg = expf(ff[e] - m);
        float c  = fg * vv[e] * kk[e];
        float den = fmaxf(fabsf(kk[e] * qq[e]), 1.f);
        float hh = sig_o * (c * qq[e]) / den;
        h[e] = hh; s += hh; ss += hh * hh;
    }
    block_reduce2(s, ss, red);
    float mean = s * (1.f / 1024.f);
    float var  = ss * (1.f / 1024.f) - mean * mean;
    float rs = rsqrtf(var + 1e-3f);
    float4 g4 = *reinterpret_cast<const float4*>(g2 + tid * 4);
    float4 bb4 = *reinterpret_cast<const float4*>(b2 + tid * 4);
    float4 a4 = ld_bf4(adj + base);
    float ga[4] = {g4.x, g4.y, g4.z, g4.w};
    float ba[4] = {bb4.x, bb4.y, bb4.z, bb4.w};
    float aa[4] = {a4.x, a4.y, a4.z, a4.w};
    float out[4];
#pragma unroll
    for (int e = 0; e < 4; e++) {
        float sig_a = 1.f / (1.f + expf(-aa[e]));
        out[e] = ((h[e] - mean) * rs * ga[e] + ba[e]) * sig_a;
    }
    uint2 u;
    u.x = pack_bf2(out[0], out[1]); u.y = pack_bf2(out[2], out[3]);
    *reinterpret_cast<uint2*>(y + base) = u;
}

// ---------------------------------------------------------------------------
// bf16 GEMM: C = A[M,K] @ B[K,N] + bias (+x for fp32 out).
// CTA 128x128x64, 256 thr, warp tile 32x64, mma.m16n8k16, ldmatrix.x4.
// 3-stage cp.async pipeline, XOR-swizzled SMEM (16B chunk ^ (row&7)).
// M%128==0, N%128==0, K%64==0.
// ---------------------------------------------------------------------------
#define STAGE_B 32768u     // A 16KB + B 16KB
#define ASTG    16384u
#define GSMEM   (3u * STAGE_B)

template<bool FP32OUT>
__global__ __launch_bounds__(256, 2) void gemm_bf16(
    const __nv_bfloat16* __restrict__ A, const __nv_bfloat16* __restrict__ Bw,
    const float* __restrict__ bias, const float* __restrict__ resid,
    void* __restrict__ Cv, int N, int K) {
    extern __shared__ char smc[];
    unsigned sbase = (unsigned)__cvta_generic_to_shared(smc);
    const int tid = threadIdx.x, lane = tid & 31, wid = tid >> 5;
    const int wm = wid & 3, wn = wid >> 2;
    const int bm = blockIdx.y * 128, bn = blockIdx.x * 128;

    float acc[2][8][4];
#pragma unroll
    for (int mi = 0; mi < 2; mi++)
#pragma unroll
        for (int ni = 0; ni < 8; ni++)
#pragma unroll
            for (int e = 0; e < 4; e++) acc[mi][ni][e] = 0.f;

    const __nv_bfloat16* ag = A + (size_t)bm * K;
    const __nv_bfloat16* bg = Bw + bn;

    auto issue = [&](int s, int k0) {
        unsigned sa = sbase + s * STAGE_B;
        unsigned sb = sa + ASTG;
#pragma unroll
        for (int i = 0; i < 4; i++) {
            int idx = tid + i * 256;
            int r = idx >> 3, c = idx & 7;
            cpasync16(sa + r * 128 + ((c ^ (r & 7)) << 4),
                      ag + (size_t)r * K + k0 + c * 8);
        }
#pragma unroll
        for (int i = 0; i < 4; i++) {
            int idx = tid + i * 256;
            int r = idx >> 4, c = idx & 15;
            cpasync16(sb + r * 256 + ((c ^ (r & 7)) << 4),
                      bg + (size_t)(k0 + r) * N + c * 8);
        }
    };

    const int nk = K >> 6;
    issue(0, 0);
    asm volatile("cp.async.commit_group;" ::: "memory");
    issue(1, 64);
    asm volatile("cp.async.commit_group;" ::: "memory");

    // ldmatrix per-thread address components
    const unsigned aoff = (unsigned)((wm * 32 + (lane & 15)) * 128);
    const unsigned asel = (lane >> 4) & 1;
    const unsigned axor = lane & 7;
    const unsigned boff = (unsigned)((((lane & 7) + ((lane >> 3) & 1) * 8)) * 256);
    const unsigned bsel = (lane >> 4) & 1;

    for (int kt = 0; kt < nk; kt++) {
        asm volatile("cp.async.wait_group 1;" ::: "memory");
        __syncthreads();
        if (kt + 2 < nk) issue((kt + 2) % 3, (kt + 2) << 6);
        asm volatile("cp.async.commit_group;" ::: "memory");

        unsigned sa = sbase + (kt % 3) * STAGE_B;
        unsigned sb = sa + ASTG;
#pragma unroll
        for (int kk = 0; kk < 4; kk++) {
            unsigned a[2][4];
#pragma unroll
            for (int mi = 0; mi < 2; mi++)
                ldsm_x4(a[mi][0], a[mi][1], a[mi][2], a[mi][3],
                        sa + aoff + mi * 2048 + ((((unsigned)(kk * 2) + asel) ^ axor) << 4));
            unsigned b[8][2];
#pragma unroll
            for (int n2 = 0; n2 < 4; n2++) {
                unsigned nch = (unsigned)(wn * 8 + n2 * 2) + bsel;
                ldsm_x4t(b[2 * n2][0], b[2 * n2][1], b[2 * n2 + 1][0], b[2 * n2 + 1][1],
                         sb + kk * 4096 + boff + ((nch ^ axor) << 4));
            }
#pragma unroll
            for (int mi = 0; mi < 2; mi++)
#pragma unroll
                for (int ni = 0; ni < 8; ni++)
                    mma_bf16(acc[mi][ni], a[mi], b[ni]);
        }
        __syncthreads();
    }

    // Epilogue
    const int r0base = bm + wm * 32 + (lane >> 2);
    const int colbase = bn + wn * 64 + (lane & 3) * 2;
    if (!FP32OUT) {
        __nv_bfloat16* C = (__nv_bfloat16*)Cv;
#pragma unroll
        for (int mi = 0; mi < 2; mi++)
#pragma unroll
            for (int ni = 0; ni < 8; ni++) {
                int r0 = r0base + mi * 16, col = colbase + ni * 8;
                float2 bb = *reinterpret_cast<const float2*>(bias + col);
                *reinterpret_cast<unsigned*>(C + (size_t)r0 * N + col) =
                    pack_bf2(acc[mi][ni][0] + bb.x, acc[mi][ni][1] + bb.y);
                *reinterpret_cast<unsigned*>(C + (size_t)(r0 + 8) * N + col) =
                    pack_bf2(acc[mi][ni][2] + bb.x, acc[mi][ni][3] + bb.y);
            }
    } else {
        float* C = (float*)Cv;
#pragma unroll
        for (int mi = 0; mi < 2; mi++)
#pragma unroll
            for (int ni = 0; ni < 8; ni++) {
                int r0 = r0base + mi * 16, col = colbase + ni * 8;
                float2 bb = *reinterpret_cast<const float2*>(bias + col);
                float2 ra = *reinterpret_cast<const float2*>(resid + (size_t)r0 * N + col);
                float2 rb = *reinterpret_cast<const float2*>(resid + (size_t)(r0 + 8) * N + col);
                float2 v0, v1;
                v0.x = acc[mi][ni][0] + bb.x + ra.x;
                v0.y = acc[mi][ni][1] + bb.y + ra.y;
                v1.x = acc[mi][ni][2] + bb.x + rb.x;
                v1.y = acc[mi][ni][3] + bb.y + rb.y;
                *reinterpret_cast<float2*>(C + (size_t)r0 * N + col) = v0;
                *reinterpret_cast<float2*>(C + (size_t)(r0 + 8) * N + col) = v1;
            }
    }
}

// ---------------------------------------------------------------------------
// Launch
// ---------------------------------------------------------------------------
extern "C" void kernel_launch(void* const* d_in, const int* in_sizes, int n_in,
                              void* d_out, int out_size) {
    const float* x      = (const float*)d_in[0];
    const float* ln1g   = (const float*)d_in[1];
    const float* ln1b   = (const float*)d_in[2];
    const float* W_up   = (const float*)d_in[3];
    const float* b_up   = (const float*)d_in[4];
    const float* W_adj  = (const float*)d_in[5];
    const float* b_adj  = (const float*)d_in[6];
    const float* W_q = (const float*)d_in[7];   const float* b_q = (const float*)d_in[8];
    const float* W_k = (const float*)d_in[9];   const float* b_k = (const float*)d_in[10];
    const float* W_v = (const float*)d_in[11];  const float* b_v = (const float*)d_in[12];
    const float* W_i = (const float*)d_in[13];  const float* b_i = (const float*)d_in[14];
    const float* W_f = (const float*)d_in[15];  const float* b_f = (const float*)d_in[16];
    const float* W_o = (const float*)d_in[17];  const float* b_o = (const float*)d_in[18];
    const float* ln2g   = (const float*)d_in[19];
    const float* ln2b   = (const float*)d_in[20];
    const float* W_down = (const float*)d_in[21];
    const float* b_down = (const float*)d_in[22];
    float* out = (float*)d_out;

    void* p;
    cudaGetSymbolAddress(&p, g_act); __nv_bfloat16* act = (__nv_bfloat16*)p;
    cudaGetSymbolAddress(&p, g_w);   __nv_bfloat16* w   = (__nv_bfloat16*)p;
    cudaGetSymbolAddress(&p, g_bcat); float* bcat = (float*)p;

    __nv_bfloat16* xn   = act;                // reused as y after up-GEMM
    __nv_bfloat16* up   = act + 1 * SZB;
    __nv_bfloat16* adj  = act + 3 * SZB;
    __nv_bfloat16* proj = act + 4 * SZB;      // [N, 6144]
    __nv_bfloat16* y    = xn;

    __nv_bfloat16* w_up   = w;
    __nv_bfloat16* w_adj  = w + 2 * M1;
    __nv_bfloat16* w_cat  = w + 4 * M1;       // [1024, 6144]
    __nv_bfloat16* w_down = w + 10 * M1;

    cudaFuncSetAttribute((const void*)gemm_bf16<false>,
                         cudaFuncAttributeMaxDynamicSharedMemorySize, GSMEM);
    cudaFuncSetAttribute((const void*)gemm_bf16<true>,
                         cudaFuncAttributeMaxDynamicSharedMemorySize, GSMEM);

    // Weight conversion / repack
    cvt_k<<<2048, 256>>>(W_up,  w_up,  (int)(2 * M1 / 4));
    cvt_k<<<2048, 256>>>(W_adj, w_adj, (int)(2 * M1 / 4));
    cvt_k<<<1024, 256>>>(W_down, w_down, (int)(M1 / 4));
    const float* Wp[6] = {W_q, W_k, W_v, W_i, W_f, W_o};
    const float* bp[6] = {b_q, b_k, b_v, b_i, b_f, b_o};
    for (int j = 0; j < 6; j++) {
        float scale = (j == 1) ? 0.125f : 1.f;   // fold 1/sqrt(64) into k
        repack_k<<<1024, 256>>>(Wp[j], w_cat + (size_t)j * 1024, scale);
        biascat_k<<<4, 256>>>(bp[j], bcat + (size_t)j * 1024, scale);
    }

    // LN1
    ln_kernel<<<NROWS, 256>>>(x, ln1g, ln1b, xn);

    // up: [N,1024] @ [1024,2048] -> bf16
    gemm_bf16<false><<<dim3(16, 128), 256, GSMEM>>>(xn, w_up, b_up, nullptr, up, 2048, 1024);

    // adj: [N,2048] @ [2048,1024] -> bf16
    gemm_bf16<false><<<dim3(8, 128), 256, GSMEM>>>(up, w_adj, b_adj, nullptr, adj, 1024, 2048);

    // proj: [N,1024] @ [1024,6144] -> bf16
    gemm_bf16<false><<<dim3(48, 128), 256, GSMEM>>>(adj, w_cat, bcat, nullptr, proj, 6144, 1024);

    // gates + LN2*sigmoid(adj)
    ew_kernel<<<NROWS, 256>>>(proj, adj, ln2g, ln2b, y);

    // down: [N,1024] @ [1024,1024] + b_down + x -> fp32 out
    gemm_bf16<true><<<dim3(8, 128), 256, GSMEM>>>(y, w_down, b_down, x, out, 1024, 1024);
}